// round 14
// baseline (speedup 1.0000x reference)
#include <cuda_runtime.h>
#include <cuda_bf16.h>

// ---------------------------------------------------------------------------
// CircularRelativePositionAttention  (B=8, S=1024, D=1024, H=16, HD=64)
// Round 13: 16-row blocks, 256 threads, 2 CTAs/SM for latency hiding.
//   p1 : sS = SCALE * Q K^T          (8 chunks x 128 keys)
//   sp : sS += P(q,512)
//   p1b: sS += scatter P(q,j) j<512  (4 chunks x 128 j)
//   p2 : 2-pass softmax (unnormalized exp kept, inv saved)
//   p4 : Co = Wfold @ rel_v          (k-split over 8 warps)
//   cv : sS -> bf16x2 hi/lo in place (normalized)
//   p3 : Co += attn @ V              (k-split over 8 warps)
//   red: smem reduction over k-splits + j=512 term, store
// ---------------------------------------------------------------------------

#define Sn    1024
#define SMASK 1023
#define SCALE 0.125f
#define SST   1028                 // 1028 % 32 == 4 -> conflict-free frag reads
#define U0    16448                // 16*1028 floats = score region
// staging (floats after U0):
//  p1/p1b: k2h 0 (128*36=4608), k2l 4608, q2h 9216 (16*36=576), q2l 9792
//  p4:     sWh 0 (16*68=1088), sWl 1088, r2h 2176 (64*68=4352), r2l 6528
//  p3:     v2h 0 (4352), v2l 4352
//  red:    0..8192
#define OFF_W512 (U0 + 10880)
#define OFF_INV  (U0 + 10896)
#define OFF_RV5  (U0 + 10912)
#define SMEM_FLOATS (U0 + 10976)
#define SMEM_BYTES (SMEM_FLOATS * 4)   // 109,696 B -> 2 CTAs/SM

// ---- bf16 helpers ---------------------------------------------------------
__device__ __forceinline__ void sp2(float x0, float x1, unsigned& uh, unsigned& ul) {
    __nv_bfloat162 hh = __floats2bfloat162_rn(x0, x1);
    float l0 = x0 - __bfloat162float(hh.x);
    float l1 = x1 - __bfloat162float(hh.y);
    __nv_bfloat162 ll = __floats2bfloat162_rn(l0, l1);
    uh = *reinterpret_cast<unsigned*>(&hh);
    ul = *reinterpret_cast<unsigned*>(&ll);
}
__device__ __forceinline__ void mma16(float* c, const unsigned* a, const unsigned* b) {
    asm volatile(
        "mma.sync.aligned.m16n8k16.row.col.f32.bf16.bf16.f32 "
        "{%0,%1,%2,%3},{%4,%5,%6,%7},{%8,%9},{%0,%1,%2,%3};"
        : "+f"(c[0]), "+f"(c[1]), "+f"(c[2]), "+f"(c[3])
        : "r"(a[0]), "r"(a[1]), "r"(a[2]), "r"(a[3]), "r"(b[0]), "r"(b[1]));
}

__global__ void __launch_bounds__(256, 2)
k_fused(const float* __restrict__ query, const float* __restrict__ key,
        const float* __restrict__ value, const float* __restrict__ relk,
        const float* __restrict__ relv, float* __restrict__ out) {
    extern __shared__ float sm[];
    unsigned* su = reinterpret_cast<unsigned*>(sm);
    float* sS = sm;                                 // 16 x 1028 fp32 scores

    const int bh = blockIdx.y, b = bh >> 4, h = bh & 15;
    const int q0 = blockIdx.x * 16;
    const int tid = threadIdx.x, w = tid >> 5, lane = tid & 31;
    const int g = lane >> 2, t4 = lane & 3;

    unsigned* k2h = su + U0;                        // [n][kp] stride 36
    unsigned* k2l = su + U0 + 4608;
    unsigned* q2h = su + U0 + 9216;                 // [r][kp] stride 36
    unsigned* q2l = su + U0 + 9792;

    // ---------------- p0: stage Q + rv512 ----------------------------------
    {
        int r = tid >> 4, v = tid & 15;
        const float4 f = *(const float4*)&query[((size_t)(b * Sn + q0 + r)) * 1024 + h * 64 + 4 * v];
        unsigned h0, l0, h1, l1;
        sp2(f.x, f.y, h0, l0); sp2(f.z, f.w, h1, l1);
        q2h[r * 36 + 2 * v] = h0; q2h[r * 36 + 2 * v + 1] = h1;
        q2l[r * 36 + 2 * v] = l0; q2l[r * 36 + 2 * v + 1] = l1;
    }
    if (tid < 64) sm[OFF_RV5 + tid] = relv[512 * 64 + tid];
    __syncthreads();

    // A fragments (m16, 4 k16 chunks)
    unsigned ah[4][4], al[4][4];
#pragma unroll
    for (int c = 0; c < 4; c++) {
        int rA = g * 36, rB = (g + 8) * 36, p = c * 8 + t4;
        ah[c][0] = q2h[rA + p];     ah[c][1] = q2h[rB + p];
        ah[c][2] = q2h[rA + p + 4]; ah[c][3] = q2h[rB + p + 4];
        al[c][0] = q2l[rA + p];     al[c][1] = q2l[rB + p];
        al[c][2] = q2l[rA + p + 4]; al[c][3] = q2l[rB + p + 4];
    }

    // ---------------- p1: sS = SCALE * Q K^T  (8 x 128 keys) ---------------
    for (int kt = 0; kt < 8; kt++) {
        __syncthreads();
#pragma unroll
        for (int i = tid; i < 2048; i += 256) {
            int n = i >> 4, v = i & 15;
            const float4 f = *(const float4*)&key[((size_t)(b * Sn + kt * 128 + n)) * 1024 + h * 64 + 4 * v];
            unsigned h0, l0, h1, l1;
            sp2(f.x, f.y, h0, l0); sp2(f.z, f.w, h1, l1);
            k2h[n * 36 + 2 * v] = h0; k2h[n * 36 + 2 * v + 1] = h1;
            k2l[n * 36 + 2 * v] = l0; k2l[n * 36 + 2 * v + 1] = l1;
        }
        __syncthreads();

        float C[2][4] = {};
#pragma unroll
        for (int c = 0; c < 4; c++) {
#pragma unroll
            for (int t = 0; t < 2; t++) {
                int n = w * 16 + t * 8 + g, p = c * 8 + t4;
                unsigned bh2[2], bl2[2];
                bh2[0] = k2h[n * 36 + p]; bh2[1] = k2h[n * 36 + p + 4];
                bl2[0] = k2l[n * 36 + p]; bl2[1] = k2l[n * 36 + p + 4];
                mma16(C[t], ah[c], bh2);
                mma16(C[t], ah[c], bl2);
                mma16(C[t], al[c], bh2);
            }
        }
#pragma unroll
        for (int t = 0; t < 2; t++) {
            int col = kt * 128 + w * 16 + t * 8 + 2 * t4;
            *(float2*)&sS[g * SST + col] =
                make_float2(C[t][0] * SCALE, C[t][1] * SCALE);
            *(float2*)&sS[(g + 8) * SST + col] =
                make_float2(C[t][2] * SCALE, C[t][3] * SCALE);
        }
    }
    __syncthreads();

    // ---------------- sp: bias P(q,512) -> col (q+512)&1023 ----------------
    {
        int r = tid >> 4, v = tid & 15;
        const float4 qf = *(const float4*)&query[((size_t)(b * Sn + q0 + r)) * 1024 + h * 64 + 4 * v];
        const float4 rf = *(const float4*)&relk[512 * 64 + 4 * v];
        float part = qf.x * rf.x + qf.y * rf.y + qf.z * rf.z + qf.w * rf.w;
#pragma unroll
        for (int o = 8; o; o >>= 1) part += __shfl_xor_sync(0xffffffffu, part, o);
        if (v == 0)
            sS[r * SST + ((q0 + r + 512) & SMASK)] += part;
    }

    // ---------------- p1b: scatter-add bias P(q,j), j in [0,512) -----------
    for (int jt = 0; jt < 4; jt++) {
        __syncthreads();
#pragma unroll
        for (int i = tid; i < 2048; i += 256) {
            int n = i >> 4, v = i & 15;
            const float4 f = *(const float4*)&relk[(jt * 128 + n) * 64 + 4 * v];
            unsigned h0, l0, h1, l1;
            sp2(f.x, f.y, h0, l0); sp2(f.z, f.w, h1, l1);
            k2h[n * 36 + 2 * v] = h0; k2h[n * 36 + 2 * v + 1] = h1;
            k2l[n * 36 + 2 * v] = l0; k2l[n * 36 + 2 * v + 1] = l1;
        }
        __syncthreads();

        float C[2][4] = {};
#pragma unroll
        for (int c = 0; c < 4; c++) {
#pragma unroll
            for (int t = 0; t < 2; t++) {
                int n = w * 16 + t * 8 + g, p = c * 8 + t4;
                unsigned bh2[2], bl2[2];
                bh2[0] = k2h[n * 36 + p]; bh2[1] = k2h[n * 36 + p + 4];
                bl2[0] = k2l[n * 36 + p]; bl2[1] = k2l[n * 36 + p + 4];
                mma16(C[t], ah[c], bh2);
                mma16(C[t], ah[c], bl2);
                mma16(C[t], al[c], bh2);
            }
        }
#pragma unroll
        for (int t = 0; t < 2; t++) {
            int j = jt * 128 + w * 16 + t * 8 + 2 * t4;   // even, <= 510
#pragma unroll
            for (int rs = 0; rs < 2; rs++) {
                int row = g + 8 * rs, qa = q0 + row;
                float c0 = C[t][2 * rs], c1 = C[t][2 * rs + 1];
                sS[row * SST + ((qa - j) & SMASK)] += c0;
                if (j > 0) sS[row * SST + ((qa + j) & SMASK)] += c0;
                sS[row * SST + ((qa - j - 1) & SMASK)] += c1;
                sS[row * SST + ((qa + j + 1) & SMASK)] += c1;
            }
        }
    }
    __syncthreads();

    // ---------------- p2: softmax (2-pass, exp kept unnormalized) ----------
    for (int r = w; r < 16; r += 8) {
        float4* row4 = (float4*)(sS + r * SST);
        float m = -1e30f;
#pragma unroll
        for (int i = 0; i < 8; i++) {
            float4 f = row4[lane + 32 * i];
            m = fmaxf(m, fmaxf(fmaxf(f.x, f.y), fmaxf(f.z, f.w)));
        }
#pragma unroll
        for (int o = 16; o; o >>= 1) m = fmaxf(m, __shfl_xor_sync(0xffffffffu, m, o));
        float s = 0.f;
#pragma unroll
        for (int i = 0; i < 8; i++) {
            float4 f = row4[lane + 32 * i];
            f.x = __expf(f.x - m); f.y = __expf(f.y - m);
            f.z = __expf(f.z - m); f.w = __expf(f.w - m);
            row4[lane + 32 * i] = f;
            s += f.x + f.y + f.z + f.w;
        }
#pragma unroll
        for (int o = 16; o; o >>= 1) s += __shfl_xor_sync(0xffffffffu, s, o);
        if (lane == 0) {
            float inv = 1.0f / s;
            sm[OFF_INV + r] = inv;
            sm[OFF_W512 + r] = sS[r * SST + ((q0 + r + 512) & SMASK)] * inv;
        }
    }
    __syncthreads();

    // ---------------- p4: Co = Wfold @ rel_v  (k-split, 4 x 128 j) ---------
    float Co[8][4] = {};
    {
        unsigned* sWh = su + U0;                    // [r][pair] stride 68
        unsigned* sWl = su + U0 + 1088;
        unsigned* r2h = su + U0 + 2176;             // [dim][pair] stride 68
        unsigned* r2l = su + U0 + 6528;
        for (int jt = 0; jt < 4; jt++) {
            __syncthreads();
            // Wfold gather: warp handles rows 2w, 2w+1; folded with inv
#pragma unroll
            for (int rr = 0; rr < 2; rr++) {
                int r = 2 * w + rr;
                float inv = sm[OFF_INV + r];
                int q = q0 + r;
                const float* rowp = sS + r * SST;
#pragma unroll
                for (int pp = lane; pp < 64; pp += 32) {
                    int j = jt * 128 + 2 * pp;          // even, <= 510
                    int j1 = j + 1;                     // odd, <= 511
                    float w0 = (j == 0) ? rowp[q & SMASK]
                             : rowp[(q - j) & SMASK] + rowp[(q + j) & SMASK];
                    float w1 = rowp[(q - j1) & SMASK] + rowp[(q + j1) & SMASK];
                    unsigned uh, ul; sp2(w0 * inv, w1 * inv, uh, ul);
                    sWh[r * 68 + pp] = uh;
                    sWl[r * 68 + pp] = ul;
                }
            }
            // relv staging: [dim][pair]
#pragma unroll
            for (int i = tid; i < 1024; i += 256) {
                int pr = i >> 4, v = i & 15;
                int j0 = jt * 128 + 2 * pr, j1 = j0 + 1;
                const float4 f0 = *(const float4*)&relv[j0 * 64 + 4 * v];
                const float4 f1 = *(const float4*)&relv[j1 * 64 + 4 * v];
                unsigned h0, l0, h1, l1, h2, l2, h3, l3;
                sp2(f0.x, f1.x, h0, l0); sp2(f0.y, f1.y, h1, l1);
                sp2(f0.z, f1.z, h2, l2); sp2(f0.w, f1.w, h3, l3);
                r2h[(4 * v) * 68 + pr] = h0; r2h[(4 * v + 1) * 68 + pr] = h1;
                r2h[(4 * v + 2) * 68 + pr] = h2; r2h[(4 * v + 3) * 68 + pr] = h3;
                r2l[(4 * v) * 68 + pr] = l0; r2l[(4 * v + 1) * 68 + pr] = l1;
                r2l[(4 * v + 2) * 68 + pr] = l2; r2l[(4 * v + 3) * 68 + pr] = l3;
            }
            __syncthreads();
            // warp w takes k16-chunk c == w of this jt (8 chunks of 8 pairs)
            {
                int pA = w * 8 + t4;
                int rA = g * 68, rB = (g + 8) * 68;
                unsigned a4h[4], a4l[4];
                a4h[0] = sWh[rA + pA];     a4h[1] = sWh[rB + pA];
                a4h[2] = sWh[rA + pA + 4]; a4h[3] = sWh[rB + pA + 4];
                a4l[0] = sWl[rA + pA];     a4l[1] = sWl[rB + pA];
                a4l[2] = sWl[rA + pA + 4]; a4l[3] = sWl[rB + pA + 4];
#pragma unroll
                for (int t = 0; t < 8; t++) {
                    int n = (t * 8 + g) * 68;
                    unsigned b4h[2], b4l[2];
                    b4h[0] = r2h[n + pA]; b4h[1] = r2h[n + pA + 4];
                    b4l[0] = r2l[n + pA]; b4l[1] = r2l[n + pA + 4];
                    mma16(Co[t], a4h, b4h);
                    mma16(Co[t], a4h, b4l);
                    mma16(Co[t], a4l, b4h);
                }
            }
        }
    }
    __syncthreads();

    // ---------------- cv: sS -> bf16x2 hi/lo in place, with inv ------------
    for (int r = w; r < 16; r += 8) {
        float inv = sm[OFF_INV + r];
        unsigned* urow = su + r * SST;
        float2* row2 = (float2*)(sS + r * SST);
        unsigned lob[16];
#pragma unroll
        for (int i = 0; i < 16; i++) {
            int p = lane + 32 * i;
            float2 xv = row2[p];
            unsigned uh, ul; sp2(xv.x * inv, xv.y * inv, uh, ul);
            urow[p] = uh;
            lob[i] = ul;
        }
        __syncwarp();
#pragma unroll
        for (int i = 0; i < 16; i++)
            urow[512 + lane + 32 * i] = lob[i];
    }

    // ---------------- p3: Co += attn @ V  (k-split, 8 x 128 keys) ----------
    {
        unsigned* v2h = su + U0;                    // [dim][pair] stride 68
        unsigned* v2l = su + U0 + 4352;
        for (int kt = 0; kt < 8; kt++) {
            __syncthreads();
#pragma unroll
            for (int i = tid; i < 1024; i += 256) {
                int pr = i >> 4, v = i & 15;
                int sq = kt * 128 + 2 * pr;
                const float4 f0 = *(const float4*)&value[((size_t)(b * Sn + sq)) * 1024 + h * 64 + 4 * v];
                const float4 f1 = *(const float4*)&value[((size_t)(b * Sn + sq + 1)) * 1024 + h * 64 + 4 * v];
                unsigned h0, l0, h1, l1, h2, l2, h3, l3;
                sp2(f0.x, f1.x, h0, l0); sp2(f0.y, f1.y, h1, l1);
                sp2(f0.z, f1.z, h2, l2); sp2(f0.w, f1.w, h3, l3);
                v2h[(4 * v) * 68 + pr] = h0; v2h[(4 * v + 1) * 68 + pr] = h1;
                v2h[(4 * v + 2) * 68 + pr] = h2; v2h[(4 * v + 3) * 68 + pr] = h3;
                v2l[(4 * v) * 68 + pr] = l0; v2l[(4 * v + 1) * 68 + pr] = l1;
                v2l[(4 * v + 2) * 68 + pr] = l2; v2l[(4 * v + 3) * 68 + pr] = l3;
            }
            __syncthreads();
            // warp w takes k16-chunk c == w (pairs w*8 .. w*8+7)
            {
                int gp = kt * 64 + w * 8 + t4;       // global key-pair
                int pl = w * 8 + t4;                 // pair in staging
                int rA = g * SST, rB = (g + 8) * SST;
                unsigned a3h[4], a3l[4];
                a3h[0] = su[rA + gp];       a3h[1] = su[rB + gp];
                a3h[2] = su[rA + gp + 4];   a3h[3] = su[rB + gp + 4];
                a3l[0] = su[rA + 512 + gp];     a3l[1] = su[rB + 512 + gp];
                a3l[2] = su[rA + 512 + gp + 4]; a3l[3] = su[rB + 512 + gp + 4];
#pragma unroll
                for (int t = 0; t < 8; t++) {
                    int n = (t * 8 + g) * 68;
                    unsigned b3h[2], b3l[2];
                    b3h[0] = v2h[n + pl]; b3h[1] = v2h[n + pl + 4];
                    b3l[0] = v2l[n + pl]; b3l[1] = v2l[n + pl + 4];
                    mma16(Co[t], a3h, b3h);
                    mma16(Co[t], a3h, b3l);
                    mma16(Co[t], a3l, b3h);
                }
            }
        }
    }
    __syncthreads();

    // ---------------- reduction over 8 k-splits + j=512 term + store -------
    {
        float* part = sm + U0;
#pragma unroll
        for (int t = 0; t < 8; t++)
#pragma unroll
            for (int e = 0; e < 4; e++)
                part[w * 1024 + (t * 4 + e) * 32 + lane] = Co[t][e];
    }
    __syncthreads();
    {
        float* part = sm + U0;
        const int t = w;                         // warp handles n-tile t
        float res[4];
#pragma unroll
        for (int e = 0; e < 4; e++) {
            float s = 0.f;
#pragma unroll
            for (int ks = 0; ks < 8; ks++)
                s += part[ks * 1024 + (t * 4 + e) * 32 + lane];
            res[e] = s;
        }
        int col = t * 8 + 2 * t4;
        float w5a = sm[OFF_W512 + g], w5b = sm[OFF_W512 + g + 8];
        float rv0 = sm[OFF_RV5 + col], rv1 = sm[OFF_RV5 + col + 1];
        size_t base = ((size_t)(b * Sn + q0 + g)) * 1024 + h * 64 + col;
        *(float2*)&out[base] = make_float2(res[0] + w5a * rv0, res[1] + w5a * rv1);
        *(float2*)&out[base + 8 * 1024] = make_float2(res[2] + w5b * rv0, res[3] + w5b * rv1);
    }
}

// ---------------------------------------------------------------------------
// inputs: 0=query 1=key 2=value 3=rel_pos_k 4=rel_pos_v ; out = f32 (B,S,D)
// ---------------------------------------------------------------------------
extern "C" void kernel_launch(void* const* d_in, const int* in_sizes, int n_in,
                              void* d_out, int out_size) {
    const float* q  = (const float*)d_in[0];
    const float* k  = (const float*)d_in[1];
    const float* v  = (const float*)d_in[2];
    const float* rk = (const float*)d_in[3];
    const float* rv = (const float*)d_in[4];
    float* out = (float*)d_out;

    cudaFuncSetAttribute(k_fused, cudaFuncAttributeMaxDynamicSharedMemorySize,
                         SMEM_BYTES);
    k_fused<<<dim3(64, 128), 256, SMEM_BYTES>>>(q, k, v, rk, rv, out);
}

// round 15
// speedup vs baseline: 1.5398x; 1.5398x over previous
#include <cuda_runtime.h>
#include <cuda_bf16.h>

// ---------------------------------------------------------------------------
// CircularRelativePositionAttention  (B=8, S=1024, D=1024, H=16, HD=64)
// Round 14: R12 structure + pre-split bf16 hi/lo operands in global scratch.
//   prep kernels: Q,K (scale folded into K), V (transposed), relk/relv.
//   fused kernel: staging = pure float4 copies; math identical to R12.
// ---------------------------------------------------------------------------

#define Sn    1024
#define SMASK 1023
#define SCALE 0.125f
#define SST   1028                 // sS row stride, 1028 % 32 == 4
#define U0    32896                // 32*1028 floats = scores region
#define OFF_W512 (U0 + 20736)
#define OFF_INV  (U0 + 20768)
#define OFF_RV5  (U0 + 20800)
#define SMEM_FLOATS (U0 + 20864)
#define SMEM_BYTES (SMEM_FLOATS * 4)   // 215,040 B

// ---- pre-split global scratch --------------------------------------------
__device__ unsigned g_qh[(size_t)128 * 1024 * 32];   // [bh][s][pair]
__device__ unsigned g_ql[(size_t)128 * 1024 * 32];
__device__ unsigned g_kh[(size_t)128 * 1024 * 32];   // K * SCALE
__device__ unsigned g_kl[(size_t)128 * 1024 * 32];
__device__ unsigned g_vh[(size_t)128 * 64 * 512];    // [bh][d][s-pair]
__device__ unsigned g_vl[(size_t)128 * 64 * 512];
__device__ unsigned g_rkh[512 * 32];                 // [j][pair], j<512
__device__ unsigned g_rkl[512 * 32];
__device__ unsigned g_rvh[64 * 384];                 // [d][j-pair], zero tail
__device__ unsigned g_rvl[64 * 384];

// ---- bf16 helpers ---------------------------------------------------------
__device__ __forceinline__ void sp2(float x0, float x1, unsigned& uh, unsigned& ul) {
    __nv_bfloat162 hh = __floats2bfloat162_rn(x0, x1);
    float l0 = x0 - __bfloat162float(hh.x);
    float l1 = x1 - __bfloat162float(hh.y);
    __nv_bfloat162 ll = __floats2bfloat162_rn(l0, l1);
    uh = *reinterpret_cast<unsigned*>(&hh);
    ul = *reinterpret_cast<unsigned*>(&ll);
}
__device__ __forceinline__ void mma16(float* c, const unsigned* a, const unsigned* b) {
    asm volatile(
        "mma.sync.aligned.m16n8k16.row.col.f32.bf16.bf16.f32 "
        "{%0,%1,%2,%3},{%4,%5,%6,%7},{%8,%9},{%0,%1,%2,%3};"
        : "+f"(c[0]), "+f"(c[1]), "+f"(c[2]), "+f"(c[3])
        : "r"(a[0]), "r"(a[1]), "r"(a[2]), "r"(a[3]), "r"(b[0]), "r"(b[1]));
}

// ---------------------------------------------------------------------------
// Prep 1: Q (which=0, scale=1) / K (which=1, scale=SCALE) -> [bh][s][pair]
// ---------------------------------------------------------------------------
__global__ void __launch_bounds__(256) k_prep_qk(const float* __restrict__ src,
                                                 float scale, int which) {
    int i = blockIdx.x * 256 + threadIdx.x;          // 8192 rows * 512 pairs
    int row = i >> 9;                                // b*1024 + s
    int hp  = i & 511;
    int hh = hp >> 5, p = hp & 31;
    const float2 f = *(const float2*)&src[((size_t)row << 10) + hh * 64 + 2 * p];
    unsigned uh, ul; sp2(f.x * scale, f.y * scale, uh, ul);
    int b = row >> 10, s = row & 1023;
    size_t o = ((size_t)((b * 16 + hh) * 1024 + s)) * 32 + p;
    if (which) { g_kh[o] = uh; g_kl[o] = ul; }
    else       { g_qh[o] = uh; g_ql[o] = ul; }
}

// ---------------------------------------------------------------------------
// Prep 2: V transpose+split -> [bh][d][s-pair]
// ---------------------------------------------------------------------------
__global__ void __launch_bounds__(256) k_prep_v(const float* __restrict__ value) {
    __shared__ float t[64][65];
    int bh = blockIdx.y, bb = bh >> 4, hh = bh & 15;
    int s0 = blockIdx.x * 64;
    int tid = threadIdx.x;
    for (int i = tid; i < 64 * 16; i += 256) {
        int s = i >> 4, v = i & 15;
        const float4 f = *(const float4*)&value[((size_t)(bb * 1024 + s0 + s)) * 1024 + hh * 64 + 4 * v];
        t[s][4 * v] = f.x; t[s][4 * v + 1] = f.y;
        t[s][4 * v + 2] = f.z; t[s][4 * v + 3] = f.w;
    }
    __syncthreads();
    for (int i = tid; i < 64 * 32; i += 256) {
        int d = i >> 5, pr = i & 31;
        unsigned uh, ul; sp2(t[2 * pr][d], t[2 * pr + 1][d], uh, ul);
        size_t o = ((size_t)(bh * 64 + d)) * 512 + (s0 >> 1) + pr;
        g_vh[o] = uh; g_vl[o] = ul;
    }
}

// ---------------------------------------------------------------------------
// Prep 3: relk [j][pair] (j<512) and relv transposed [d][j-pair] (pr<256)
// ---------------------------------------------------------------------------
__global__ void __launch_bounds__(256) k_prep_rel(const float* __restrict__ relk,
                                                  const float* __restrict__ relv) {
    int i = blockIdx.x * 256 + threadIdx.x;          // 16384
    {
        int j = i >> 5, p = i & 31;
        const float2 f = *(const float2*)&relk[j * 64 + 2 * p];
        unsigned uh, ul; sp2(f.x, f.y, uh, ul);
        g_rkh[i] = uh; g_rkl[i] = ul;
    }
    {
        int d = i >> 8, pr = i & 255;
        float a = relv[(2 * pr) * 64 + d];
        float c = relv[(2 * pr + 1) * 64 + d];
        unsigned uh, ul; sp2(a, c, uh, ul);
        g_rvh[d * 384 + pr] = uh; g_rvl[d * 384 + pr] = ul;
    }
}

// ---------------------------------------------------------------------------
// Fused kernel (R12 math, copy-only staging)
// ---------------------------------------------------------------------------
__global__ void __launch_bounds__(512, 1)
k_fused(const float* __restrict__ query, const float* __restrict__ relk,
        const float* __restrict__ relv, float* __restrict__ out) {
    extern __shared__ float sm[];
    unsigned* su = reinterpret_cast<unsigned*>(sm);
    float* sS = sm;                                 // 32 x 1028 fp32 scores

    const int bh = blockIdx.y, b = bh >> 4, h = bh & 15;
    const int q0 = blockIdx.x * 32;
    const int tid = threadIdx.x, w = tid >> 5, lane = tid & 31;
    const int g = lane >> 2, t4 = lane & 3;

    unsigned* k2h = su + U0;                        // [n][kp] stride 36
    unsigned* k2l = su + U0 + 9216;
    unsigned* q2h = su + U0 + 18432;                // [r][kp] stride 36
    unsigned* q2l = su + U0 + 19584;

    // ---------------- p0: copy pre-split Q + rv512 -------------------------
    {
        int plane = tid >> 8, f = tid & 255;
        int r = f >> 3, pc = (f & 7) * 4;
        const unsigned* gsrc = plane ? g_ql : g_qh;
        unsigned* dst = plane ? q2l : q2h;
        *(float4*)&dst[r * 36 + pc] =
            *(const float4*)&gsrc[((size_t)(bh * 1024 + q0 + r)) * 32 + pc];
    }
    if (tid < 64) sm[OFF_RV5 + tid] = relv[512 * 64 + tid];
    __syncthreads();

    // A fragments for m32 (both halves), 4 k16 chunks
    unsigned ah2[2][4][4], al2[2][4][4];
#pragma unroll
    for (int mh = 0; mh < 2; mh++)
#pragma unroll
        for (int c = 0; c < 4; c++) {
            int rA = (mh * 16 + g) * 36, rB = (mh * 16 + g + 8) * 36, p = c * 8 + t4;
            ah2[mh][c][0] = q2h[rA + p];     ah2[mh][c][1] = q2h[rB + p];
            ah2[mh][c][2] = q2h[rA + p + 4]; ah2[mh][c][3] = q2h[rB + p + 4];
            al2[mh][c][0] = q2l[rA + p];     al2[mh][c][1] = q2l[rB + p];
            al2[mh][c][2] = q2l[rA + p + 4]; al2[mh][c][3] = q2l[rB + p + 4];
        }

    // ---------------- p1: sS = (SCALE*Q) K^T  (4 x 256 keys) ---------------
    for (int kt = 0; kt < 4; kt++) {
        __syncthreads();
#pragma unroll
        for (int i = tid; i < 4096; i += 512) {
            int plane = i >> 11, f = i & 2047;
            int n = f >> 3, pc = (f & 7) * 4;
            const unsigned* gsrc = plane ? g_kl : g_kh;
            unsigned* dst = plane ? k2l : k2h;
            *(float4*)&dst[n * 36 + pc] =
                *(const float4*)&gsrc[((size_t)(bh * 1024 + kt * 256 + n)) * 32 + pc];
        }
        __syncthreads();

        float C[2][2][4] = {};
#pragma unroll
        for (int c = 0; c < 4; c++) {
#pragma unroll
            for (int t = 0; t < 2; t++) {
                int n = w * 16 + t * 8 + g, p = c * 8 + t4;
                unsigned bh2[2], bl2[2];
                bh2[0] = k2h[n * 36 + p]; bh2[1] = k2h[n * 36 + p + 4];
                bl2[0] = k2l[n * 36 + p]; bl2[1] = k2l[n * 36 + p + 4];
#pragma unroll
                for (int mh = 0; mh < 2; mh++) {
                    mma16(C[mh][t], ah2[mh][c], bh2);
                    mma16(C[mh][t], ah2[mh][c], bl2);
                    mma16(C[mh][t], al2[mh][c], bh2);
                }
            }
        }
#pragma unroll
        for (int mh = 0; mh < 2; mh++)
#pragma unroll
            for (int t = 0; t < 2; t++) {
                int col = kt * 256 + w * 16 + t * 8 + 2 * t4;
                int row = mh * 16 + g;
                *(float2*)&sS[row * SST + col] = make_float2(C[mh][t][0], C[mh][t][1]);
                *(float2*)&sS[(row + 8) * SST + col] = make_float2(C[mh][t][2], C[mh][t][3]);
            }
    }
    __syncthreads();

    // ---------------- sp: bias P(q,512) -> col (q+512)&1023 ----------------
    {
        int r = tid >> 4, v = tid & 15;
        const float4 qf = *(const float4*)&query[((size_t)(b * Sn + q0 + r)) * 1024 + h * 64 + 4 * v];
        const float4 rf = *(const float4*)&relk[512 * 64 + 4 * v];
        float part = qf.x * rf.x + qf.y * rf.y + qf.z * rf.z + qf.w * rf.w;
#pragma unroll
        for (int o = 8; o; o >>= 1) part += __shfl_xor_sync(0xffffffffu, part, o);
        if (v == 0)
            sS[r * SST + ((q0 + r + 512) & SMASK)] += part;
    }

    // ---------------- p1b: scatter-add bias P(q,j), j in [0,512) -----------
    for (int jt = 0; jt < 2; jt++) {
        __syncthreads();
#pragma unroll
        for (int i = tid; i < 4096; i += 512) {
            int plane = i >> 11, f = i & 2047;
            int n = f >> 3, pc = (f & 7) * 4;
            const unsigned* gsrc = plane ? g_rkl : g_rkh;
            unsigned* dst = plane ? k2l : k2h;
            *(float4*)&dst[n * 36 + pc] =
                *(const float4*)&gsrc[(size_t)(jt * 256 + n) * 32 + pc];
        }
        __syncthreads();

        float C[2][2][4] = {};
#pragma unroll
        for (int c = 0; c < 4; c++) {
#pragma unroll
            for (int t = 0; t < 2; t++) {
                int n = w * 16 + t * 8 + g, p = c * 8 + t4;
                unsigned bh2[2], bl2[2];
                bh2[0] = k2h[n * 36 + p]; bh2[1] = k2h[n * 36 + p + 4];
                bl2[0] = k2l[n * 36 + p]; bl2[1] = k2l[n * 36 + p + 4];
#pragma unroll
                for (int mh = 0; mh < 2; mh++) {
                    mma16(C[mh][t], ah2[mh][c], bh2);
                    mma16(C[mh][t], ah2[mh][c], bl2);
                    mma16(C[mh][t], al2[mh][c], bh2);
                }
            }
        }
#pragma unroll
        for (int mh = 0; mh < 2; mh++)
#pragma unroll
            for (int t = 0; t < 2; t++) {
                int j = jt * 256 + w * 16 + t * 8 + 2 * t4;
#pragma unroll
                for (int rs = 0; rs < 2; rs++) {
                    int row = mh * 16 + g + 8 * rs, qa = q0 + row;
                    float c0 = C[mh][t][2 * rs], c1 = C[mh][t][2 * rs + 1];
                    sS[row * SST + ((qa - j) & SMASK)] += c0;
                    if (j > 0) sS[row * SST + ((qa + j) & SMASK)] += c0;
                    sS[row * SST + ((qa - j - 1) & SMASK)] += c1;
                    sS[row * SST + ((qa + j + 1) & SMASK)] += c1;
                }
            }
    }
    __syncthreads();

    // ---------------- p2: softmax (2-pass, exp kept unnormalized) ----------
    for (int r = w; r < 32; r += 16) {
        float4* row4 = (float4*)(sS + r * SST);
        float m = -1e30f;
#pragma unroll
        for (int i = 0; i < 8; i++) {
            float4 f = row4[lane + 32 * i];
            m = fmaxf(m, fmaxf(fmaxf(f.x, f.y), fmaxf(f.z, f.w)));
        }
#pragma unroll
        for (int o = 16; o; o >>= 1) m = fmaxf(m, __shfl_xor_sync(0xffffffffu, m, o));
        float s = 0.f;
#pragma unroll
        for (int i = 0; i < 8; i++) {
            float4 f = row4[lane + 32 * i];
            f.x = __expf(f.x - m); f.y = __expf(f.y - m);
            f.z = __expf(f.z - m); f.w = __expf(f.w - m);
            row4[lane + 32 * i] = f;
            s += f.x + f.y + f.z + f.w;
        }
#pragma unroll
        for (int o = 16; o; o >>= 1) s += __shfl_xor_sync(0xffffffffu, s, o);
        if (lane == 0) {
            float inv = 1.0f / s;
            sm[OFF_INV + r] = inv;
            sm[OFF_W512 + r] = sS[r * SST + ((q0 + r + 512) & SMASK)] * inv;
        }
    }
    __syncthreads();

    // ---------------- p4: Co = Wfold @ rel_v  (k-split, 3 x 192 j) ---------
    float Co[8][4] = {};
    {
        unsigned* sWh = su + U0;                    // [r][pair] stride 100
        unsigned* sWl = su + U0 + 3200;
        unsigned* r2h = su + U0 + 6400;             // [dim][pair] stride 100
        unsigned* r2l = su + U0 + 12800;
        const int mh = w & 1, ks = w >> 1;
        for (int jt = 0; jt < 3; jt++) {
            __syncthreads();
            // Wfold gather (warp handles rows 2w, 2w+1), folded with inv
#pragma unroll
            for (int rr = 0; rr < 2; rr++) {
                int r = 2 * w + rr;
                float inv = sm[OFF_INV + r];
                int q = q0 + r;
                const float* rowp = sS + r * SST;
                for (int pp = lane; pp < 96; pp += 32) {
                    int j = jt * 192 + 2 * pp;
                    float w0 = 0.f, w1 = 0.f;
                    if (j == 0) w0 = rowp[q];
                    else if (j < 512) w0 = rowp[(q - j) & SMASK] + rowp[(q + j) & SMASK];
                    int j1 = j + 1;
                    if (j1 < 512) w1 = rowp[(q - j1) & SMASK] + rowp[(q + j1) & SMASK];
                    unsigned uh, ul; sp2(w0 * inv, w1 * inv, uh, ul);
                    sWh[r * 100 + pp] = uh;
                    sWl[r * 100 + pp] = ul;
                }
            }
            // relv staging: pure copy of pre-split planes
#pragma unroll
            for (int i = tid; i < 3072; i += 512) {
                int plane = (i >= 1536) ? 1 : 0;
                int f = plane ? i - 1536 : i;
                int d = f / 24, rem = f - d * 24, pc = rem * 4;
                const unsigned* gsrc = plane ? g_rvl : g_rvh;
                unsigned* dst = plane ? r2l : r2h;
                *(float4*)&dst[d * 100 + pc] =
                    *(const float4*)&gsrc[d * 384 + jt * 96 + pc];
            }
            __syncthreads();
#pragma unroll
            for (int c = 0; c < 12; c++) {
                if (((jt * 12 + c) & 7) != ks) continue;
                int pA = c * 8 + t4;
                int rA = (mh * 16 + g) * 100, rB = rA + 8 * 100;
                unsigned a4h[4], a4l[4];
                a4h[0] = sWh[rA + pA];     a4h[1] = sWh[rB + pA];
                a4h[2] = sWh[rA + pA + 4]; a4h[3] = sWh[rB + pA + 4];
                a4l[0] = sWl[rA + pA];     a4l[1] = sWl[rB + pA];
                a4l[2] = sWl[rA + pA + 4]; a4l[3] = sWl[rB + pA + 4];
#pragma unroll
                for (int t = 0; t < 8; t++) {
                    int n = (t * 8 + g) * 100;
                    unsigned b4h[2], b4l[2];
                    b4h[0] = r2h[n + pA]; b4h[1] = r2h[n + pA + 4];
                    b4l[0] = r2l[n + pA]; b4l[1] = r2l[n + pA + 4];
                    mma16(Co[t], a4h, b4h);
                    mma16(Co[t], a4h, b4l);
                    mma16(Co[t], a4l, b4h);
                }
            }
        }
    }
    __syncthreads();

    // ---------------- cv: sS -> bf16x2 hi/lo in place, with inv ------------
    for (int r = w; r < 32; r += 16) {
        float inv = sm[OFF_INV + r];
        unsigned* urow = su + r * SST;
        float2* row2 = (float2*)(sS + r * SST);
        unsigned lob[16];
#pragma unroll
        for (int i = 0; i < 16; i++) {
            int p = lane + 32 * i;
            float2 xv = row2[p];
            unsigned uh, ul; sp2(xv.x * inv, xv.y * inv, uh, ul);
            urow[p] = uh;
            lob[i] = ul;
        }
        __syncwarp();
#pragma unroll
        for (int i = 0; i < 16; i++)
            urow[512 + lane + 32 * i] = lob[i];
    }

    // ---------------- p3: Co += attn @ V  (k-split, 4 x 256 keys) ----------
    {
        unsigned* v2h = su + U0;                    // [dim][pair] stride 132
        unsigned* v2l = su + U0 + 8448;
        const int mh = w & 1, ks = w >> 1;
        for (int kt = 0; kt < 4; kt++) {
            __syncthreads();
#pragma unroll
            for (int i = tid; i < 4096; i += 512) {
                int plane = i >> 11, f = i & 2047;
                int d = f >> 5, pc = (f & 31) * 4;
                const unsigned* gsrc = plane ? g_vl : g_vh;
                unsigned* dst = plane ? v2l : v2h;
                *(float4*)&dst[d * 132 + pc] =
                    *(const float4*)&gsrc[((size_t)(bh * 64 + d)) * 512 + kt * 128 + pc];
            }
            __syncthreads();
#pragma unroll
            for (int c = 0; c < 16; c++) {
                if ((c & 7) != ks) continue;
                int gp = kt * 128 + c * 8 + t4;      // global key-pair
                int pl = c * 8 + t4;                 // local pair in staging
                int rA = (mh * 16 + g) * SST, rB = rA + 8 * SST;
                unsigned a3h[4], a3l[4];
                a3h[0] = su[rA + gp];       a3h[1] = su[rB + gp];
                a3h[2] = su[rA + gp + 4];   a3h[3] = su[rB + gp + 4];
                a3l[0] = su[rA + 512 + gp];     a3l[1] = su[rB + 512 + gp];
                a3l[2] = su[rA + 512 + gp + 4]; a3l[3] = su[rB + 512 + gp + 4];
#pragma unroll
                for (int t = 0; t < 8; t++) {
                    int n = (t * 8 + g) * 132;
                    unsigned b3h[2], b3l[2];
                    b3h[0] = v2h[n + pl]; b3h[1] = v2h[n + pl + 4];
                    b3l[0] = v2l[n + pl]; b3l[1] = v2l[n + pl + 4];
                    mma16(Co[t], a3h, b3h);
                    mma16(Co[t], a3h, b3l);
                    mma16(Co[t], a3l, b3h);
                }
            }
        }
    }
    __syncthreads();

    // ---------------- reduction over 8 k-splits + j=512 term + store -------
    {
        float* part = sm + U0;
#pragma unroll
        for (int t = 0; t < 8; t++)
#pragma unroll
            for (int e = 0; e < 4; e++)
                part[w * 1024 + (t * 4 + e) * 32 + lane] = Co[t][e];
    }
    __syncthreads();
    {
        float* part = sm + U0;
        const int mh = w & 1, t = w >> 1;
        float res[4];
#pragma unroll
        for (int e = 0; e < 4; e++) {
            float s = 0.f;
#pragma unroll
            for (int ks = 0; ks < 8; ks++)
                s += part[(mh + 2 * ks) * 1024 + (t * 4 + e) * 32 + lane];
            res[e] = s;
        }
        int col = t * 8 + 2 * t4;
        int row0 = mh * 16 + g;
        float w5a = sm[OFF_W512 + row0], w5b = sm[OFF_W512 + row0 + 8];
        float rv0 = sm[OFF_RV5 + col], rv1 = sm[OFF_RV5 + col + 1];
        size_t base = ((size_t)(b * Sn + q0 + row0)) * 1024 + h * 64 + col;
        *(float2*)&out[base] = make_float2(res[0] + w5a * rv0, res[1] + w5a * rv1);
        *(float2*)&out[base + 8 * 1024] = make_float2(res[2] + w5b * rv0, res[3] + w5b * rv1);
    }
}

// ---------------------------------------------------------------------------
// inputs: 0=query 1=key 2=value 3=rel_pos_k 4=rel_pos_v ; out = f32 (B,S,D)
// ---------------------------------------------------------------------------
extern "C" void kernel_launch(void* const* d_in, const int* in_sizes, int n_in,
                              void* d_out, int out_size) {
    const float* q  = (const float*)d_in[0];
    const float* k  = (const float*)d_in[1];
    const float* v  = (const float*)d_in[2];
    const float* rk = (const float*)d_in[3];
    const float* rv = (const float*)d_in[4];
    float* out = (float*)d_out;

    cudaFuncSetAttribute(k_fused, cudaFuncAttributeMaxDynamicSharedMemorySize,
                         SMEM_BYTES);

    k_prep_qk<<<16384, 256>>>(q, 1.0f, 0);
    k_prep_qk<<<16384, 256>>>(k, SCALE, 1);
    k_prep_v <<<dim3(16, 128), 256>>>(v);
    k_prep_rel<<<64, 256>>>(rk, rv);
    k_fused<<<dim3(32, 128), 512, SMEM_BYTES>>>(q, rk, rv, out);
}

// round 16
// speedup vs baseline: 1.6050x; 1.0424x over previous
#include <cuda_runtime.h>
#include <cuda_bf16.h>

// ---------------------------------------------------------------------------
// CircularRelativePositionAttention  (B=8, S=1024, D=1024, H=16, HD=64)
// Round 15: pre-split uint2 (hi,lo) operands; p1/p1b B-fragments loaded
// directly from L2 (no smem staging, no internal barriers).
// ---------------------------------------------------------------------------

#define Sn    1024
#define SMASK 1023
#define SCALE 0.125f
#define SST   1028                 // sS row stride, 1028 % 32 == 4
#define U0    32896                // 32*1028 floats = scores region
#define OFF_W512 (U0 + 20736)
#define OFF_INV  (U0 + 20768)
#define OFF_RV5  (U0 + 20800)
#define SMEM_FLOATS (U0 + 20864)
#define SMEM_BYTES (SMEM_FLOATS * 4)   // 215,040 B

// ---- pre-split global scratch (hi,lo packed as uint2) ---------------------
__device__ uint2 g_q2[(size_t)128 * 1024 * 32];      // [bh][s][pair]
__device__ uint2 g_k2[(size_t)128 * 1024 * 32];      // K * SCALE
__device__ uint2 g_rk2[512 * 32];                    // [j][pair], j<512
__device__ unsigned g_vh[(size_t)128 * 64 * 512];    // [bh][d][s-pair]
__device__ unsigned g_vl[(size_t)128 * 64 * 512];
__device__ unsigned g_rvh[64 * 384];                 // [d][j-pair], zero tail
__device__ unsigned g_rvl[64 * 384];

// ---- bf16 helpers ---------------------------------------------------------
__device__ __forceinline__ void sp2(float x0, float x1, unsigned& uh, unsigned& ul) {
    __nv_bfloat162 hh = __floats2bfloat162_rn(x0, x1);
    float l0 = x0 - __bfloat162float(hh.x);
    float l1 = x1 - __bfloat162float(hh.y);
    __nv_bfloat162 ll = __floats2bfloat162_rn(l0, l1);
    uh = *reinterpret_cast<unsigned*>(&hh);
    ul = *reinterpret_cast<unsigned*>(&ll);
}
__device__ __forceinline__ void mma16(float* c, const unsigned* a, const unsigned* b) {
    asm volatile(
        "mma.sync.aligned.m16n8k16.row.col.f32.bf16.bf16.f32 "
        "{%0,%1,%2,%3},{%4,%5,%6,%7},{%8,%9},{%0,%1,%2,%3};"
        : "+f"(c[0]), "+f"(c[1]), "+f"(c[2]), "+f"(c[3])
        : "r"(a[0]), "r"(a[1]), "r"(a[2]), "r"(a[3]), "r"(b[0]), "r"(b[1]));
}

// ---------------------------------------------------------------------------
// Prep 1: Q (which=0, scale=1) / K (which=1, scale=SCALE) -> uint2 planes
// ---------------------------------------------------------------------------
__global__ void __launch_bounds__(256) k_prep_qk(const float* __restrict__ src,
                                                 float scale, int which) {
    int i = blockIdx.x * 256 + threadIdx.x;          // 8192 rows * 512 pairs
    int row = i >> 9;                                // b*1024 + s
    int hp  = i & 511;
    int hh = hp >> 5, p = hp & 31;
    const float2 f = *(const float2*)&src[((size_t)row << 10) + hh * 64 + 2 * p];
    unsigned uh, ul; sp2(f.x * scale, f.y * scale, uh, ul);
    int b = row >> 10, s = row & 1023;
    size_t o = ((size_t)((b * 16 + hh) * 1024 + s)) * 32 + p;
    if (which) g_k2[o] = make_uint2(uh, ul);
    else       g_q2[o] = make_uint2(uh, ul);
}

// ---------------------------------------------------------------------------
// Prep 2: V transpose+split -> [bh][d][s-pair]
// ---------------------------------------------------------------------------
__global__ void __launch_bounds__(256) k_prep_v(const float* __restrict__ value) {
    __shared__ float t[64][65];
    int bh = blockIdx.y, bb = bh >> 4, hh = bh & 15;
    int s0 = blockIdx.x * 64;
    int tid = threadIdx.x;
    for (int i = tid; i < 64 * 16; i += 256) {
        int s = i >> 4, v = i & 15;
        const float4 f = *(const float4*)&value[((size_t)(bb * 1024 + s0 + s)) * 1024 + hh * 64 + 4 * v];
        t[s][4 * v] = f.x; t[s][4 * v + 1] = f.y;
        t[s][4 * v + 2] = f.z; t[s][4 * v + 3] = f.w;
    }
    __syncthreads();
    for (int i = tid; i < 64 * 32; i += 256) {
        int d = i >> 5, pr = i & 31;
        unsigned uh, ul; sp2(t[2 * pr][d], t[2 * pr + 1][d], uh, ul);
        size_t o = ((size_t)(bh * 64 + d)) * 512 + (s0 >> 1) + pr;
        g_vh[o] = uh; g_vl[o] = ul;
    }
}

// ---------------------------------------------------------------------------
// Prep 3: relk [j][pair] uint2 (j<512), relv transposed [d][j-pair]
// ---------------------------------------------------------------------------
__global__ void __launch_bounds__(256) k_prep_rel(const float* __restrict__ relk,
                                                  const float* __restrict__ relv) {
    int i = blockIdx.x * 256 + threadIdx.x;          // 16384
    {
        int j = i >> 5, p = i & 31;
        const float2 f = *(const float2*)&relk[j * 64 + 2 * p];
        unsigned uh, ul; sp2(f.x, f.y, uh, ul);
        g_rk2[i] = make_uint2(uh, ul);
    }
    {
        int d = i >> 8, pr = i & 255;
        float a = relv[(2 * pr) * 64 + d];
        float c = relv[(2 * pr + 1) * 64 + d];
        unsigned uh, ul; sp2(a, c, uh, ul);
        g_rvh[d * 384 + pr] = uh; g_rvl[d * 384 + pr] = ul;
    }
}

// ---------------------------------------------------------------------------
// Fused kernel
// ---------------------------------------------------------------------------
__global__ void __launch_bounds__(512, 1)
k_fused(const float* __restrict__ query, const float* __restrict__ relk,
        const float* __restrict__ relv, float* __restrict__ out) {
    extern __shared__ float sm[];
    unsigned* su = reinterpret_cast<unsigned*>(sm);
    float* sS = sm;                                 // 32 x 1028 fp32 scores

    const int bh = blockIdx.y, b = bh >> 4, h = bh & 15;
    const int q0 = blockIdx.x * 32;
    const int tid = threadIdx.x, w = tid >> 5, lane = tid & 31;
    const int g = lane >> 2, t4 = lane & 3;

    if (tid < 64) sm[OFF_RV5 + tid] = relv[512 * 64 + tid];

    // ---------------- A fragments straight from global uint2 planes --------
    unsigned ah2[2][4][4], al2[2][4][4];
#pragma unroll
    for (int mh = 0; mh < 2; mh++) {
        const uint2* qa = &g_q2[((size_t)(bh * 1024 + q0 + mh * 16 + g)) * 32];
        const uint2* qb = qa + (size_t)8 * 32;
#pragma unroll
        for (int c = 0; c < 4; c++) {
            int p = c * 8 + t4;
            uint2 a0 = qa[p], b0 = qb[p], a1 = qa[p + 4], b1 = qb[p + 4];
            ah2[mh][c][0] = a0.x; ah2[mh][c][1] = b0.x;
            ah2[mh][c][2] = a1.x; ah2[mh][c][3] = b1.x;
            al2[mh][c][0] = a0.y; al2[mh][c][1] = b0.y;
            al2[mh][c][2] = a1.y; al2[mh][c][3] = b1.y;
        }
    }

    // ---------------- p1: sS = (SCALE*Q) K^T  — no barriers ----------------
#pragma unroll
    for (int kt = 0; kt < 4; kt++) {
        float C[2][2][4] = {};
#pragma unroll
        for (int t = 0; t < 2; t++) {
            const uint2* kp = &g_k2[((size_t)(bh * 1024 + kt * 256 + w * 16 + t * 8 + g)) * 32];
            uint2 u0[4], u1[4];
#pragma unroll
            for (int c = 0; c < 4; c++) {
                u0[c] = kp[c * 8 + t4];
                u1[c] = kp[c * 8 + t4 + 4];
            }
#pragma unroll
            for (int c = 0; c < 4; c++) {
                unsigned bh2[2] = {u0[c].x, u1[c].x};
                unsigned bl2[2] = {u0[c].y, u1[c].y};
#pragma unroll
                for (int mh = 0; mh < 2; mh++) {
                    mma16(C[mh][t], ah2[mh][c], bh2);
                    mma16(C[mh][t], ah2[mh][c], bl2);
                    mma16(C[mh][t], al2[mh][c], bh2);
                }
            }
        }
#pragma unroll
        for (int mh = 0; mh < 2; mh++)
#pragma unroll
            for (int t = 0; t < 2; t++) {
                int col = kt * 256 + w * 16 + t * 8 + 2 * t4;
                int row = mh * 16 + g;
                *(float2*)&sS[row * SST + col] = make_float2(C[mh][t][0], C[mh][t][1]);
                *(float2*)&sS[(row + 8) * SST + col] = make_float2(C[mh][t][2], C[mh][t][3]);
            }
    }
    __syncthreads();

    // ---------------- sp: bias P(q,512) -> col (q+512)&1023 ----------------
    {
        int r = tid >> 4, v = tid & 15;
        const float4 qf = *(const float4*)&query[((size_t)(b * Sn + q0 + r)) * 1024 + h * 64 + 4 * v];
        const float4 rf = *(const float4*)&relk[512 * 64 + 4 * v];
        float part = qf.x * rf.x + qf.y * rf.y + qf.z * rf.z + qf.w * rf.w;
#pragma unroll
        for (int o = 8; o; o >>= 1) part += __shfl_xor_sync(0xffffffffu, part, o);
        if (v == 0)
            sS[r * SST + ((q0 + r + 512) & SMASK)] += part;
    }

    // ---------------- p1b: scatter-add bias P(q,j), j<512 — no barriers ----
#pragma unroll
    for (int jt = 0; jt < 2; jt++) {
        float C[2][2][4] = {};
#pragma unroll
        for (int t = 0; t < 2; t++) {
            const uint2* kp = &g_rk2[(jt * 256 + w * 16 + t * 8 + g) * 32];
            uint2 u0[4], u1[4];
#pragma unroll
            for (int c = 0; c < 4; c++) {
                u0[c] = kp[c * 8 + t4];
                u1[c] = kp[c * 8 + t4 + 4];
            }
#pragma unroll
            for (int c = 0; c < 4; c++) {
                unsigned bh2[2] = {u0[c].x, u1[c].x};
                unsigned bl2[2] = {u0[c].y, u1[c].y};
#pragma unroll
                for (int mh = 0; mh < 2; mh++) {
                    mma16(C[mh][t], ah2[mh][c], bh2);
                    mma16(C[mh][t], ah2[mh][c], bl2);
                    mma16(C[mh][t], al2[mh][c], bh2);
                }
            }
        }
#pragma unroll
        for (int mh = 0; mh < 2; mh++)
#pragma unroll
            for (int t = 0; t < 2; t++) {
                int j = jt * 256 + w * 16 + t * 8 + 2 * t4;
#pragma unroll
                for (int rs = 0; rs < 2; rs++) {
                    int row = mh * 16 + g + 8 * rs, qa = q0 + row;
                    float c0 = C[mh][t][2 * rs], c1 = C[mh][t][2 * rs + 1];
                    sS[row * SST + ((qa - j) & SMASK)] += c0;
                    if (j > 0) sS[row * SST + ((qa + j) & SMASK)] += c0;
                    sS[row * SST + ((qa - j - 1) & SMASK)] += c1;
                    sS[row * SST + ((qa + j + 1) & SMASK)] += c1;
                }
            }
    }
    __syncthreads();

    // ---------------- p2: softmax (2-pass, exp kept unnormalized) ----------
    for (int r = w; r < 32; r += 16) {
        float4* row4 = (float4*)(sS + r * SST);
        float m = -1e30f;
#pragma unroll
        for (int i = 0; i < 8; i++) {
            float4 f = row4[lane + 32 * i];
            m = fmaxf(m, fmaxf(fmaxf(f.x, f.y), fmaxf(f.z, f.w)));
        }
#pragma unroll
        for (int o = 16; o; o >>= 1) m = fmaxf(m, __shfl_xor_sync(0xffffffffu, m, o));
        float s = 0.f;
#pragma unroll
        for (int i = 0; i < 8; i++) {
            float4 f = row4[lane + 32 * i];
            f.x = __expf(f.x - m); f.y = __expf(f.y - m);
            f.z = __expf(f.z - m); f.w = __expf(f.w - m);
            row4[lane + 32 * i] = f;
            s += f.x + f.y + f.z + f.w;
        }
#pragma unroll
        for (int o = 16; o; o >>= 1) s += __shfl_xor_sync(0xffffffffu, s, o);
        if (lane == 0) {
            float inv = 1.0f / s;
            sm[OFF_INV + r] = inv;
            sm[OFF_W512 + r] = sS[r * SST + ((q0 + r + 512) & SMASK)] * inv;
        }
    }
    __syncthreads();

    // ---------------- p4: Co = Wfold @ rel_v  (k-split, 3 x 192 j) ---------
    float Co[8][4] = {};
    {
        unsigned* sWh = su + U0;                    // [r][pair] stride 100
        unsigned* sWl = su + U0 + 3200;
        unsigned* r2h = su + U0 + 6400;             // [dim][pair] stride 100
        unsigned* r2l = su + U0 + 12800;
        const int mh = w & 1, ks = w >> 1;
        for (int jt = 0; jt < 3; jt++) {
            __syncthreads();
            // Wfold gather (warp handles rows 2w, 2w+1), folded with inv
#pragma unroll
            for (int rr = 0; rr < 2; rr++) {
                int r = 2 * w + rr;
                float inv = sm[OFF_INV + r];
                int q = q0 + r;
                const float* rowp = sS + r * SST;
                for (int pp = lane; pp < 96; pp += 32) {
                    int j = jt * 192 + 2 * pp;
                    float w0 = 0.f, w1 = 0.f;
                    if (j == 0) w0 = rowp[q];
                    else if (j < 512) w0 = rowp[(q - j) & SMASK] + rowp[(q + j) & SMASK];
                    int j1 = j + 1;
                    if (j1 < 512) w1 = rowp[(q - j1) & SMASK] + rowp[(q + j1) & SMASK];
                    unsigned uh, ul; sp2(w0 * inv, w1 * inv, uh, ul);
                    sWh[r * 100 + pp] = uh;
                    sWl[r * 100 + pp] = ul;
                }
            }
            // relv staging: pure copy of pre-split planes
#pragma unroll
            for (int i = tid; i < 3072; i += 512) {
                int plane = (i >= 1536) ? 1 : 0;
                int f = plane ? i - 1536 : i;
                int d = f / 24, rem = f - d * 24, pc = rem * 4;
                const unsigned* gsrc = plane ? g_rvl : g_rvh;
                unsigned* dst = plane ? r2l : r2h;
                *(float4*)&dst[d * 100 + pc] =
                    *(const float4*)&gsrc[d * 384 + jt * 96 + pc];
            }
            __syncthreads();
#pragma unroll
            for (int c = 0; c < 12; c++) {
                if (((jt * 12 + c) & 7) != ks) continue;
                int pA = c * 8 + t4;
                int rA = (mh * 16 + g) * 100, rB = rA + 8 * 100;
                unsigned a4h[4], a4l[4];
                a4h[0] = sWh[rA + pA];     a4h[1] = sWh[rB + pA];
                a4h[2] = sWh[rA + pA + 4]; a4h[3] = sWh[rB + pA + 4];
                a4l[0] = sWl[rA + pA];     a4l[1] = sWl[rB + pA];
                a4l[2] = sWl[rA + pA + 4]; a4l[3] = sWl[rB + pA + 4];
#pragma unroll
                for (int t = 0; t < 8; t++) {
                    int n = (t * 8 + g) * 100;
                    unsigned b4h[2], b4l[2];
                    b4h[0] = r2h[n + pA]; b4h[1] = r2h[n + pA + 4];
                    b4l[0] = r2l[n + pA]; b4l[1] = r2l[n + pA + 4];
                    mma16(Co[t], a4h, b4h);
                    mma16(Co[t], a4h, b4l);
                    mma16(Co[t], a4l, b4h);
                }
            }
        }
    }
    __syncthreads();

    // ---------------- cv: sS -> bf16x2 hi/lo in place, with inv ------------
    for (int r = w; r < 32; r += 16) {
        float inv = sm[OFF_INV + r];
        unsigned* urow = su + r * SST;
        float2* row2 = (float2*)(sS + r * SST);
        unsigned lob[16];
#pragma unroll
        for (int i = 0; i < 16; i++) {
            int p = lane + 32 * i;
            float2 xv = row2[p];
            unsigned uh, ul; sp2(xv.x * inv, xv.y * inv, uh, ul);
            urow[p] = uh;
            lob[i] = ul;
        }
        __syncwarp();
#pragma unroll
        for (int i = 0; i < 16; i++)
            urow[512 + lane + 32 * i] = lob[i];
    }

    // ---------------- p3: Co += attn @ V  (k-split, 4 x 256 keys) ----------
    {
        unsigned* v2h = su + U0;                    // [dim][pair] stride 132
        unsigned* v2l = su + U0 + 8448;
        const int mh = w & 1, ks = w >> 1;
        for (int kt = 0; kt < 4; kt++) {
            __syncthreads();
#pragma unroll
            for (int i = tid; i < 4096; i += 512) {
                int plane = i >> 11, f = i & 2047;
                int d = f >> 5, pc = (f & 31) * 4;
                const unsigned* gsrc = plane ? g_vl : g_vh;
                unsigned* dst = plane ? v2l : v2h;
                *(float4*)&dst[d * 132 + pc] =
                    *(const float4*)&gsrc[((size_t)(bh * 64 + d)) * 512 + kt * 128 + pc];
            }
            __syncthreads();
#pragma unroll
            for (int c = 0; c < 16; c++) {
                if ((c & 7) != ks) continue;
                int gp = kt * 128 + c * 8 + t4;      // global key-pair
                int pl = c * 8 + t4;                 // local pair in staging
                int rA = (mh * 16 + g) * SST, rB = rA + 8 * SST;
                unsigned a3h[4], a3l[4];
                a3h[0] = su[rA + gp];       a3h[1] = su[rB + gp];
                a3h[2] = su[rA + gp + 4];   a3h[3] = su[rB + gp + 4];
                a3l[0] = su[rA + 512 + gp];     a3l[1] = su[rB + 512 + gp];
                a3l[2] = su[rA + 512 + gp + 4]; a3l[3] = su[rB + 512 + gp + 4];
#pragma unroll
                for (int t = 0; t < 8; t++) {
                    int n = (t * 8 + g) * 132;
                    unsigned b3h[2], b3l[2];
                    b3h[0] = v2h[n + pl]; b3h[1] = v2h[n + pl + 4];
                    b3l[0] = v2l[n + pl]; b3l[1] = v2l[n + pl + 4];
                    mma16(Co[t], a3h, b3h);
                    mma16(Co[t], a3h, b3l);
                    mma16(Co[t], a3l, b3h);
                }
            }
        }
    }
    __syncthreads();

    // ---------------- reduction over 8 k-splits + j=512 term + store -------
    {
        float* part = sm + U0;
#pragma unroll
        for (int t = 0; t < 8; t++)
#pragma unroll
            for (int e = 0; e < 4; e++)
                part[w * 1024 + (t * 4 + e) * 32 + lane] = Co[t][e];
    }
    __syncthreads();
    {
        float* part = sm + U0;
        const int mh = w & 1, t = w >> 1;
        float res[4];
#pragma unroll
        for (int e = 0; e < 4; e++) {
            float s = 0.f;
#pragma unroll
            for (int ks = 0; ks < 8; ks++)
                s += part[(mh + 2 * ks) * 1024 + (t * 4 + e) * 32 + lane];
            res[e] = s;
        }
        int col = t * 8 + 2 * t4;
        int row0 = mh * 16 + g;
        float w5a = sm[OFF_W512 + row0], w5b = sm[OFF_W512 + row0 + 8];
        float rv0 = sm[OFF_RV5 + col], rv1 = sm[OFF_RV5 + col + 1];
        size_t base = ((size_t)(b * Sn + q0 + row0)) * 1024 + h * 64 + col;
        *(float2*)&out[base] = make_float2(res[0] + w5a * rv0, res[1] + w5a * rv1);
        *(float2*)&out[base + 8 * 1024] = make_float2(res[2] + w5b * rv0, res[3] + w5b * rv1);
    }
}

// ---------------------------------------------------------------------------
// inputs: 0=query 1=key 2=value 3=rel_pos_k 4=rel_pos_v ; out = f32 (B,S,D)
// ---------------------------------------------------------------------------
extern "C" void kernel_launch(void* const* d_in, const int* in_sizes, int n_in,
                              void* d_out, int out_size) {
    const float* q  = (const float*)d_in[0];
    const float* k  = (const float*)d_in[1];
    const float* v  = (const float*)d_in[2];
    const float* rk = (const float*)d_in[3];
    const float* rv = (const float*)d_in[4];
    float* out = (float*)d_out;

    cudaFuncSetAttribute(k_fused, cudaFuncAttributeMaxDynamicSharedMemorySize,
                         SMEM_BYTES);

    k_prep_qk<<<16384, 256>>>(q, 1.0f, 0);
    k_prep_qk<<<16384, 256>>>(k, SCALE, 1);
    k_prep_v <<<dim3(16, 128), 256>>>(v);
    k_prep_rel<<<64, 256>>>(rk, rv);
    k_fused<<<dim3(32, 128), 512, SMEM_BYTES>>>(q, rk, rv, out);
}

// round 17
// speedup vs baseline: 1.7576x; 1.0951x over previous
#include <cuda_runtime.h>
#include <cuda_bf16.h>

// ---------------------------------------------------------------------------
// CircularRelativePositionAttention  (B=8, S=1024, D=1024, H=16, HD=64)
// Round 16: barrier-minimal fused kernel. p1/p1b/p3/p4 all load operand
// fragments directly from pre-split uint2 global planes; p3/p4 A-fragments
// (attn / Wfold) are built on the fly in the owning warp. 5 barriers total.
// ---------------------------------------------------------------------------

#define Sn    1024
#define SMASK 1023
#define SCALE 0.125f
#define SST   1028                 // sS row stride, 1028 % 32 == 4
#define U0    32896                // 32*1028 floats = scores region
#define OFF_W512 (U0)
#define OFF_INV  (U0 + 32)
#define OFF_RV5  (U0 + 64)
#define SMEM_FLOATS (U0 + 128)
#define SMEM_BYTES (SMEM_FLOATS * 4)   // 132,096 B

// ---- pre-split global scratch (hi,lo packed as uint2) ---------------------
__device__ uint2 g_q2[(size_t)128 * 1024 * 32];      // [bh][s][pair]
__device__ uint2 g_k2[(size_t)128 * 1024 * 32];      // K * SCALE
__device__ uint2 g_rk2[512 * 32];                    // [j][pair], j<512
__device__ uint2 g_v2[(size_t)128 * 64 * 512];       // [bh][d][s-pair]
__device__ uint2 g_rv2[64 * 256];                    // [d][j-pair], j<512

// ---- bf16 helpers ---------------------------------------------------------
__device__ __forceinline__ void sp2(float x0, float x1, unsigned& uh, unsigned& ul) {
    __nv_bfloat162 hh = __floats2bfloat162_rn(x0, x1);
    float l0 = x0 - __bfloat162float(hh.x);
    float l1 = x1 - __bfloat162float(hh.y);
    __nv_bfloat162 ll = __floats2bfloat162_rn(l0, l1);
    uh = *reinterpret_cast<unsigned*>(&hh);
    ul = *reinterpret_cast<unsigned*>(&ll);
}
__device__ __forceinline__ void mma16(float* c, const unsigned* a, const unsigned* b) {
    asm volatile(
        "mma.sync.aligned.m16n8k16.row.col.f32.bf16.bf16.f32 "
        "{%0,%1,%2,%3},{%4,%5,%6,%7},{%8,%9},{%0,%1,%2,%3};"
        : "+f"(c[0]), "+f"(c[1]), "+f"(c[2]), "+f"(c[3])
        : "r"(a[0]), "r"(a[1]), "r"(a[2]), "r"(a[3]), "r"(b[0]), "r"(b[1]));
}

// ---------------------------------------------------------------------------
// Prep 1: Q (which=0, scale=1) / K (which=1, scale=SCALE) -> uint2 planes
// ---------------------------------------------------------------------------
__global__ void __launch_bounds__(256) k_prep_qk(const float* __restrict__ src,
                                                 float scale, int which) {
    int i = blockIdx.x * 256 + threadIdx.x;          // 8192 rows * 512 pairs
    int row = i >> 9;
    int hp  = i & 511;
    int hh = hp >> 5, p = hp & 31;
    const float2 f = *(const float2*)&src[((size_t)row << 10) + hh * 64 + 2 * p];
    unsigned uh, ul; sp2(f.x * scale, f.y * scale, uh, ul);
    int b = row >> 10, s = row & 1023;
    size_t o = ((size_t)((b * 16 + hh) * 1024 + s)) * 32 + p;
    if (which) g_k2[o] = make_uint2(uh, ul);
    else       g_q2[o] = make_uint2(uh, ul);
}

// ---------------------------------------------------------------------------
// Prep 2: V transpose+split -> [bh][d][s-pair] uint2
// ---------------------------------------------------------------------------
__global__ void __launch_bounds__(256) k_prep_v(const float* __restrict__ value) {
    __shared__ float t[64][65];
    int bh = blockIdx.y, bb = bh >> 4, hh = bh & 15;
    int s0 = blockIdx.x * 64;
    int tid = threadIdx.x;
    for (int i = tid; i < 64 * 16; i += 256) {
        int s = i >> 4, v = i & 15;
        const float4 f = *(const float4*)&value[((size_t)(bb * 1024 + s0 + s)) * 1024 + hh * 64 + 4 * v];
        t[s][4 * v] = f.x; t[s][4 * v + 1] = f.y;
        t[s][4 * v + 2] = f.z; t[s][4 * v + 3] = f.w;
    }
    __syncthreads();
    for (int i = tid; i < 64 * 32; i += 256) {
        int d = i >> 5, pr = i & 31;
        unsigned uh, ul; sp2(t[2 * pr][d], t[2 * pr + 1][d], uh, ul);
        g_v2[((size_t)(bh * 64 + d)) * 512 + (s0 >> 1) + pr] = make_uint2(uh, ul);
    }
}

// ---------------------------------------------------------------------------
// Prep 3: relk [j][pair] uint2 (j<512), relv transposed [d][j-pair] uint2
// ---------------------------------------------------------------------------
__global__ void __launch_bounds__(256) k_prep_rel(const float* __restrict__ relk,
                                                  const float* __restrict__ relv) {
    int i = blockIdx.x * 256 + threadIdx.x;          // 16384
    {
        int j = i >> 5, p = i & 31;
        const float2 f = *(const float2*)&relk[j * 64 + 2 * p];
        unsigned uh, ul; sp2(f.x, f.y, uh, ul);
        g_rk2[i] = make_uint2(uh, ul);
    }
    {
        int d = i >> 8, pr = i & 255;
        float a = relv[(2 * pr) * 64 + d];
        float c = relv[(2 * pr + 1) * 64 + d];
        unsigned uh, ul; sp2(a, c, uh, ul);
        g_rv2[d * 256 + pr] = make_uint2(uh, ul);
    }
}

// ---------------------------------------------------------------------------
// Fused kernel (5 barriers)
// ---------------------------------------------------------------------------
__global__ void __launch_bounds__(512, 1)
k_fused(const float* __restrict__ query, const float* __restrict__ relk,
        const float* __restrict__ relv, float* __restrict__ out) {
    extern __shared__ float sm[];
    float* sS = sm;                                 // 32 x 1028 fp32 scores

    const int bh = blockIdx.y, b = bh >> 4, h = bh & 15;
    const int q0 = blockIdx.x * 32;
    const int tid = threadIdx.x, w = tid >> 5, lane = tid & 31;
    const int g = lane >> 2, t4 = lane & 3;

    if (tid < 64) sm[OFF_RV5 + tid] = relv[512 * 64 + tid];

    // ---------------- A fragments straight from global uint2 planes --------
    unsigned ah2[2][4][4], al2[2][4][4];
#pragma unroll
    for (int mh = 0; mh < 2; mh++) {
        const uint2* qa = &g_q2[((size_t)(bh * 1024 + q0 + mh * 16 + g)) * 32];
        const uint2* qb = qa + (size_t)8 * 32;
#pragma unroll
        for (int c = 0; c < 4; c++) {
            int p = c * 8 + t4;
            uint2 a0 = qa[p], b0 = qb[p], a1 = qa[p + 4], b1 = qb[p + 4];
            ah2[mh][c][0] = a0.x; ah2[mh][c][1] = b0.x;
            ah2[mh][c][2] = a1.x; ah2[mh][c][3] = b1.x;
            al2[mh][c][0] = a0.y; al2[mh][c][1] = b0.y;
            al2[mh][c][2] = a1.y; al2[mh][c][3] = b1.y;
        }
    }

    // ---------------- p1: sS = (SCALE*Q) K^T  — no barriers ----------------
#pragma unroll
    for (int kt = 0; kt < 4; kt++) {
        float C[2][2][4] = {};
#pragma unroll
        for (int t = 0; t < 2; t++) {
            const uint2* kp = &g_k2[((size_t)(bh * 1024 + kt * 256 + w * 16 + t * 8 + g)) * 32];
            uint2 u0[4], u1[4];
#pragma unroll
            for (int c = 0; c < 4; c++) {
                u0[c] = kp[c * 8 + t4];
                u1[c] = kp[c * 8 + t4 + 4];
            }
#pragma unroll
            for (int c = 0; c < 4; c++) {
                unsigned bh2[2] = {u0[c].x, u1[c].x};
                unsigned bl2[2] = {u0[c].y, u1[c].y};
#pragma unroll
                for (int mh = 0; mh < 2; mh++) {
                    mma16(C[mh][t], ah2[mh][c], bh2);
                    mma16(C[mh][t], ah2[mh][c], bl2);
                    mma16(C[mh][t], al2[mh][c], bh2);
                }
            }
        }
#pragma unroll
        for (int mh = 0; mh < 2; mh++)
#pragma unroll
            for (int t = 0; t < 2; t++) {
                int col = kt * 256 + w * 16 + t * 8 + 2 * t4;
                int row = mh * 16 + g;
                *(float2*)&sS[row * SST + col] = make_float2(C[mh][t][0], C[mh][t][1]);
                *(float2*)&sS[(row + 8) * SST + col] = make_float2(C[mh][t][2], C[mh][t][3]);
            }
    }
    __syncthreads();                                               // B1

    // ---------------- sp: bias P(q,512) -> col (q+512)&1023 ----------------
    {
        int r = tid >> 4, v = tid & 15;
        const float4 qf = *(const float4*)&query[((size_t)(b * Sn + q0 + r)) * 1024 + h * 64 + 4 * v];
        const float4 rf = *(const float4*)&relk[512 * 64 + 4 * v];
        float part = qf.x * rf.x + qf.y * rf.y + qf.z * rf.z + qf.w * rf.w;
#pragma unroll
        for (int o = 8; o; o >>= 1) part += __shfl_xor_sync(0xffffffffu, part, o);
        if (v == 0)
            sS[r * SST + ((q0 + r + 512) & SMASK)] += part;
    }

    // ---------------- p1b: scatter-add bias P(q,j), j<512 — no barriers ----
#pragma unroll
    for (int jt = 0; jt < 2; jt++) {
        float C[2][2][4] = {};
#pragma unroll
        for (int t = 0; t < 2; t++) {
            const uint2* kp = &g_rk2[(jt * 256 + w * 16 + t * 8 + g) * 32];
            uint2 u0[4], u1[4];
#pragma unroll
            for (int c = 0; c < 4; c++) {
                u0[c] = kp[c * 8 + t4];
                u1[c] = kp[c * 8 + t4 + 4];
            }
#pragma unroll
            for (int c = 0; c < 4; c++) {
                unsigned bh2[2] = {u0[c].x, u1[c].x};
                unsigned bl2[2] = {u0[c].y, u1[c].y};
#pragma unroll
                for (int mh = 0; mh < 2; mh++) {
                    mma16(C[mh][t], ah2[mh][c], bh2);
                    mma16(C[mh][t], ah2[mh][c], bl2);
                    mma16(C[mh][t], al2[mh][c], bh2);
                }
            }
        }
#pragma unroll
        for (int mh = 0; mh < 2; mh++)
#pragma unroll
            for (int t = 0; t < 2; t++) {
                int j = jt * 256 + w * 16 + t * 8 + 2 * t4;
#pragma unroll
                for (int rs = 0; rs < 2; rs++) {
                    int row = mh * 16 + g + 8 * rs, qa = q0 + row;
                    float c0 = C[mh][t][2 * rs], c1 = C[mh][t][2 * rs + 1];
                    sS[row * SST + ((qa - j) & SMASK)] += c0;
                    if (j > 0) sS[row * SST + ((qa + j) & SMASK)] += c0;
                    sS[row * SST + ((qa - j - 1) & SMASK)] += c1;
                    sS[row * SST + ((qa + j + 1) & SMASK)] += c1;
                }
            }
    }
    __syncthreads();                                               // B2

    // ---------------- p2: softmax (2-pass, exp kept unnormalized) ----------
    for (int r = w; r < 32; r += 16) {
        float4* row4 = (float4*)(sS + r * SST);
        float m = -1e30f;
#pragma unroll
        for (int i = 0; i < 8; i++) {
            float4 f = row4[lane + 32 * i];
            m = fmaxf(m, fmaxf(fmaxf(f.x, f.y), fmaxf(f.z, f.w)));
        }
#pragma unroll
        for (int o = 16; o; o >>= 1) m = fmaxf(m, __shfl_xor_sync(0xffffffffu, m, o));
        float s = 0.f;
#pragma unroll
        for (int i = 0; i < 8; i++) {
            float4 f = row4[lane + 32 * i];
            f.x = __expf(f.x - m); f.y = __expf(f.y - m);
            f.z = __expf(f.z - m); f.w = __expf(f.w - m);
            row4[lane + 32 * i] = f;
            s += f.x + f.y + f.z + f.w;
        }
#pragma unroll
        for (int o = 16; o; o >>= 1) s += __shfl_xor_sync(0xffffffffu, s, o);
        if (lane == 0) {
            float inv = 1.0f / s;
            sm[OFF_INV + r] = inv;
            sm[OFF_W512 + r] = sS[r * SST + ((q0 + r + 512) & SMASK)] * inv;
        }
    }
    __syncthreads();                                               // B3

    // ---------------- p4' + p3': barrier-free accumulation -----------------
    float Co[8][4] = {};
    const int mh = w & 1, ks = w >> 1;
    const int rA = mh * 16 + g, rB = rA + 8;
    const float invA = sm[OFF_INV + rA], invB = sm[OFF_INV + rB];
    const float* rowA = sS + rA * SST;
    const float* rowB = sS + rB * SST;
    const int qA = q0 + rA, qB = q0 + rB;

    // p4': Co = Wfold @ rel_v  (4 chunks of 8 j-pairs per warp)
#pragma unroll
    for (int cc = 0; cc < 4; cc++) {
        int c = ks + 8 * cc;
        int P = c * 8 + t4;
        // fold weights for j = 2P, 2P+1, 2P+8, 2P+9  (all <= 511)
        int j0 = 2 * P, j1 = j0 + 1, j2 = j0 + 8, j3 = j0 + 9;
        float wA0 = (j0 == 0) ? rowA[qA]
                              : rowA[(qA - j0) & SMASK] + rowA[(qA + j0) & SMASK];
        float wA1 = rowA[(qA - j1) & SMASK] + rowA[(qA + j1) & SMASK];
        float wA2 = rowA[(qA - j2) & SMASK] + rowA[(qA + j2) & SMASK];
        float wA3 = rowA[(qA - j3) & SMASK] + rowA[(qA + j3) & SMASK];
        float wB0 = (j0 == 0) ? rowB[qB]
                              : rowB[(qB - j0) & SMASK] + rowB[(qB + j0) & SMASK];
        float wB1 = rowB[(qB - j1) & SMASK] + rowB[(qB + j1) & SMASK];
        float wB2 = rowB[(qB - j2) & SMASK] + rowB[(qB + j2) & SMASK];
        float wB3 = rowB[(qB - j3) & SMASK] + rowB[(qB + j3) & SMASK];
        unsigned a4h[4], a4l[4];
        sp2(wA0 * invA, wA1 * invA, a4h[0], a4l[0]);
        sp2(wB0 * invB, wB1 * invB, a4h[1], a4l[1]);
        sp2(wA2 * invA, wA3 * invA, a4h[2], a4l[2]);
        sp2(wB2 * invB, wB3 * invB, a4h[3], a4l[3]);
#pragma unroll
        for (int t = 0; t < 8; t++) {
            const uint2* rp = &g_rv2[(t * 8 + g) * 256];
            uint2 u0 = rp[P], u1 = rp[P + 4];
            unsigned b4h[2] = {u0.x, u1.x};
            unsigned b4l[2] = {u0.y, u1.y};
            mma16(Co[t], a4h, b4h);
            mma16(Co[t], a4h, b4l);
            mma16(Co[t], a4l, b4h);
        }
    }

    // p3': Co += attn @ V  (8 chunks of 8 s-pairs per warp)
#pragma unroll
    for (int cc = 0; cc < 8; cc++) {
        int c = ks + 8 * cc;
        int P = c * 8 + t4;
        float2 x0 = *(const float2*)&rowA[2 * P];
        float2 x1 = *(const float2*)&rowB[2 * P];
        float2 x2 = *(const float2*)&rowA[2 * P + 8];
        float2 x3 = *(const float2*)&rowB[2 * P + 8];
        unsigned a3h[4], a3l[4];
        sp2(x0.x * invA, x0.y * invA, a3h[0], a3l[0]);
        sp2(x1.x * invB, x1.y * invB, a3h[1], a3l[1]);
        sp2(x2.x * invA, x2.y * invA, a3h[2], a3l[2]);
        sp2(x3.x * invB, x3.y * invB, a3h[3], a3l[3]);
#pragma unroll
        for (int t = 0; t < 8; t++) {
            const uint2* vp = &g_v2[((size_t)(bh * 64 + t * 8 + g)) * 512];
            uint2 u0 = vp[P], u1 = vp[P + 4];
            unsigned b3h[2] = {u0.x, u1.x};
            unsigned b3l[2] = {u0.y, u1.y};
            mma16(Co[t], a3h, b3h);
            mma16(Co[t], a3h, b3l);
            mma16(Co[t], a3l, b3h);
        }
    }
    __syncthreads();                                               // B4

    // ---------------- reduction over 8 k-splits + j=512 term + store -------
    {
        float* part = sm;                            // reuse score region
#pragma unroll
        for (int t = 0; t < 8; t++)
#pragma unroll
            for (int e = 0; e < 4; e++)
                part[w * 1024 + (t * 4 + e) * 32 + lane] = Co[t][e];
    }
    __syncthreads();                                               // B5
    {
        float* part = sm;
        const int mh2 = w & 1, t = w >> 1;
        float res[4];
#pragma unroll
        for (int e = 0; e < 4; e++) {
            float s = 0.f;
#pragma unroll
            for (int k2 = 0; k2 < 8; k2++)
                s += part[(mh2 + 2 * k2) * 1024 + (t * 4 + e) * 32 + lane];
            res[e] = s;
        }
        int col = t * 8 + 2 * t4;
        int row0 = mh2 * 16 + g;
        float w5a = sm[OFF_W512 + row0], w5b = sm[OFF_W512 + row0 + 8];
        float rv0 = sm[OFF_RV5 + col], rv1 = sm[OFF_RV5 + col + 1];
        size_t base = ((size_t)(b * Sn + q0 + row0)) * 1024 + h * 64 + col;
        *(float2*)&out[base] = make_float2(res[0] + w5a * rv0, res[1] + w5a * rv1);
        *(float2*)&out[base + 8 * 1024] = make_float2(res[2] + w5b * rv0, res[3] + w5b * rv1);
    }
}

// ---------------------------------------------------------------------------
// inputs: 0=query 1=key 2=value 3=rel_pos_k 4=rel_pos_v ; out = f32 (B,S,D)
// ---------------------------------------------------------------------------
extern "C" void kernel_launch(void* const* d_in, const int* in_sizes, int n_in,
                              void* d_out, int out_size) {
    const float* q  = (const float*)d_in[0];
    const float* k  = (const float*)d_in[1];
    const float* v  = (const float*)d_in[2];
    const float* rk = (const float*)d_in[3];
    const float* rv = (const float*)d_in[4];
    float* out = (float*)d_out;

    cudaFuncSetAttribute(k_fused, cudaFuncAttributeMaxDynamicSharedMemorySize,
                         SMEM_BYTES);

    k_prep_qk<<<16384, 256>>>(q, 1.0f, 0);
    k_prep_qk<<<16384, 256>>>(k, SCALE, 1);
    k_prep_v <<<dim3(16, 128), 256>>>(v);
    k_prep_rel<<<64, 256>>>(rk, rv);
    k_fused<<<dim3(32, 128), 512, SMEM_BYTES>>>(q, rk, rv, out);
}